// round 13
// baseline (speedup 1.0000x reference)
#include <cuda_runtime.h>
#include <cuda_fp16.h>
#include <math.h>
#include <stdint.h>

#define NROWS 4096
#define DIM   1024
#define TEMPF 0.05f
#define INVT  20.0f
#define EPSF  1e-8f

#define KSTORE 1024
#define BM 128
#define BN 128
#define BK 64
#define NCHUNKS (KSTORE / BK)       // 16
#define NSTAGES 3
#define A_STAGE_BYTES (BM * 128)
#define B_STAGE_BYTES (BN * 128)
#define STAGE_BYTES   (A_STAGE_BYTES + B_STAGE_BYTES)
#define SMEM_DYN_BYTES (NSTAGES * STAGE_BYTES)          // 96 KB -> 2 CTAs/SM

#define NTILES (NROWS / BN)          // 32 column tiles
#define PARTW  (NTILES * 2)          // 64 partials per row

// -------- device scratch --------
__device__ __half g_a[(size_t)NROWS * KSTORE];
__device__ __half g_b[(size_t)NROWS * KSTORE];
__device__ __align__(16) float g_pe[(size_t)NROWS * PARTW];
__device__ __align__(16) float g_pl[(size_t)NROWS * PARTW];
__device__ __align__(16) float g_row_val[NROWS];

// ============================================================
// helpers
// ============================================================
__device__ __forceinline__ uint32_t smem_u32(const void* p) {
    uint32_t a;
    asm("{ .reg .u64 t; cvta.to.shared.u64 t, %1; cvt.u32.u64 %0, t; }"
        : "=r"(a) : "l"(p));
    return a;
}

#define SW128(x) ((x) ^ (((x) >> 3) & 0x70))

__device__ __forceinline__ void cp_async16(uint32_t dst, const void* src) {
    asm volatile("cp.async.cg.shared.global [%0], [%1], 16;\n" :: "r"(dst), "l"(src));
}

__device__ __forceinline__ void ldsm_x4(uint32_t addr, uint32_t& r0, uint32_t& r1,
                                        uint32_t& r2, uint32_t& r3) {
    asm volatile("ldmatrix.sync.aligned.m8n8.x4.shared.b16 {%0,%1,%2,%3}, [%4];"
                 : "=r"(r0), "=r"(r1), "=r"(r2), "=r"(r3) : "r"(addr));
}

__device__ __forceinline__ void mma16816(float& c0, float& c1, float& c2, float& c3,
                                         uint32_t a0, uint32_t a1, uint32_t a2, uint32_t a3,
                                         uint32_t b0, uint32_t b1) {
    asm volatile(
        "mma.sync.aligned.m16n8k16.row.col.f32.f16.f16.f32 "
        "{%0,%1,%2,%3}, {%4,%5,%6,%7}, {%8,%9}, {%0,%1,%2,%3};"
        : "+f"(c0), "+f"(c1), "+f"(c2), "+f"(c3)
        : "r"(a0), "r"(a1), "r"(a2), "r"(a3), "r"(b0), "r"(b1));
}

// ============================================================
// Kernel 1: row-normalize -> fp16
// ============================================================
__global__ __launch_bounds__(256)
void normalize_kernel(const float* __restrict__ c, const float* __restrict__ ch) {
    int row = blockIdx.x;
    bool isC = (row < NROWS);
    int r = isC ? row : row - NROWS;
    const float4* srow = (const float4*)((isC ? c : ch) + (size_t)r * DIM);

    int t = threadIdx.x;
    float4 v = srow[t];
    float ssq = v.x * v.x + v.y * v.y + v.z * v.z + v.w * v.w;

    #pragma unroll
    for (int o = 16; o > 0; o >>= 1)
        ssq += __shfl_xor_sync(0xffffffffu, ssq, o);

    __shared__ float wsum[8];
    if ((t & 31) == 0) wsum[t >> 5] = ssq;
    __syncthreads();
    float tot = 0.f;
    #pragma unroll
    for (int w = 0; w < 8; w++) tot += wsum[w];

    float rinv = 1.0f / fmaxf(sqrtf(tot), EPSF);

    union { __half h[4]; uint2 u; } ph;
    ph.h[0] = __float2half_rn(v.x * rinv);
    ph.h[1] = __float2half_rn(v.y * rinv);
    ph.h[2] = __float2half_rn(v.z * rinv);
    ph.h[3] = __float2half_rn(v.w * rinv);

    __half* dst = (isC ? g_a : g_b) + (size_t)r * KSTORE + t * 4;
    *(uint2*)dst = ph.u;
}

// ============================================================
// Kernel 2: fused fp16 GEMM + sim + y_true + softmax partials
// (256,2) bound keeps 2 CTAs/SM; y predicates are already
// computed for the pl sums, so y costs only the stores.
// ============================================================
__device__ __forceinline__ void load_chunk(const __half* gA, const __half* gB,
                                           int kc, uint32_t sA, uint32_t sB, int t) {
    int ke = kc * BK;
    #pragma unroll
    for (int i = 0; i < 4; i++) {
        int idx = i * 256 + t;
        int r = idx >> 3, cb = idx & 7;
        cp_async16(sA + SW128(r * 128 + cb * 16), gA + (size_t)r * KSTORE + ke + cb * 8);
    }
    #pragma unroll
    for (int i = 0; i < 4; i++) {
        int idx = i * 256 + t;
        int r = idx >> 3, cb = idx & 7;
        cp_async16(sB + SW128(r * 128 + cb * 16), gB + (size_t)r * KSTORE + ke + cb * 8);
    }
    asm volatile("cp.async.commit_group;\n" ::: "memory");
}

__global__ __launch_bounds__(256, 2)
void gemm_fused_kernel(float* __restrict__ out,
                       const int* __restrict__ labels,
                       float* __restrict__ y_out) {
    extern __shared__ char dyn_smem[];
    __shared__ int slr[BM];
    __shared__ int slc[BN];

    const int t    = threadIdx.x;
    const int wid  = t >> 5;
    const int lane = t & 31;
    const int wm   = wid >> 1;
    const int wn   = wid & 1;
    const int bx   = blockIdx.x;
    const int by   = blockIdx.y;

    uint32_t smem = smem_u32(dyn_smem);

    if (t < BM) slr[t] = labels[by * BM + t];
    else if (t < BM + BN) slc[t - BM] = labels[bx * BN + (t - BM)];

    const __half* gA = g_a + (size_t)by * BM * KSTORE;
    const __half* gB = g_b + (size_t)bx * BN * KSTORE;

    float acc[2][8][4];
    #pragma unroll
    for (int mi = 0; mi < 2; mi++)
        #pragma unroll
        for (int ni = 0; ni < 8; ni++)
            #pragma unroll
            for (int q = 0; q < 4; q++) acc[mi][ni][q] = 0.f;

    load_chunk(gA, gB, 0, smem, smem + A_STAGE_BYTES, t);
    load_chunk(gA, gB, 1, smem + STAGE_BYTES, smem + STAGE_BYTES + A_STAGE_BYTES, t);

    const int a_row_in16 = lane & 15;
    const int a_kadd     = ((lane >> 4) & 1) * 16;
    const int b_row_in16 = (lane & 7) + (((lane >> 4) & 1) << 3);
    const int b_kadd     = ((lane >> 3) & 1) * 16;

    for (int kc = 0; kc < NCHUNKS; kc++) {
        if (kc + 2 < NCHUNKS) {
            int s = (kc + 2) % NSTAGES;
            load_chunk(gA, gB, kc + 2, smem + s * STAGE_BYTES,
                       smem + s * STAGE_BYTES + A_STAGE_BYTES, t);
        } else {
            asm volatile("cp.async.commit_group;\n" ::: "memory");
        }

        asm volatile("cp.async.wait_group 2;\n" ::: "memory");
        __syncthreads();

        uint32_t sA = smem + (kc % NSTAGES) * STAGE_BYTES;
        uint32_t sB = sA + A_STAGE_BYTES;

        #pragma unroll
        for (int ks = 0; ks < 4; ks++) {
            const int kb = ks * 32;

            uint32_t af[2][4];
            #pragma unroll
            for (int mi = 0; mi < 2; mi++) {
                int row = wm * 32 + mi * 16 + a_row_in16;
                ldsm_x4(sA + SW128(row * 128 + kb + a_kadd),
                        af[mi][0], af[mi][1], af[mi][2], af[mi][3]);
            }
            uint32_t bf[4][4];
            #pragma unroll
            for (int nj = 0; nj < 4; nj++) {
                int row = wn * 64 + nj * 16 + b_row_in16;
                ldsm_x4(sB + SW128(row * 128 + kb + b_kadd),
                        bf[nj][0], bf[nj][1], bf[nj][2], bf[nj][3]);
            }
            #pragma unroll
            for (int mi = 0; mi < 2; mi++)
                #pragma unroll
                for (int nj = 0; nj < 4; nj++) {
                    mma16816(acc[mi][nj * 2 + 0][0], acc[mi][nj * 2 + 0][1],
                             acc[mi][nj * 2 + 0][2], acc[mi][nj * 2 + 0][3],
                             af[mi][0], af[mi][1], af[mi][2], af[mi][3],
                             bf[nj][0], bf[nj][1]);
                    mma16816(acc[mi][nj * 2 + 1][0], acc[mi][nj * 2 + 1][1],
                             acc[mi][nj * 2 + 1][2], acc[mi][nj * 2 + 1][3],
                             af[mi][0], af[mi][1], af[mi][2], af[mi][3],
                             bf[nj][2], bf[nj][3]);
                }
        }
        __syncthreads();
    }

    // ---------- fused epilogue: sim + y_true + softmax partials ----------
    const int rb = wm * 32 + (lane >> 2);
    const int cb = wn * 64 + (lane & 3) * 2;

    float pe[4] = {0.f, 0.f, 0.f, 0.f};
    float pl[4] = {0.f, 0.f, 0.f, 0.f};

    #pragma unroll
    for (int mi = 0; mi < 2; mi++) {
        const int sl = mi * 2, sh = mi * 2 + 1;
        const int lr_lo = slr[rb + mi * 16];
        const int lr_hi = slr[rb + mi * 16 + 8];
        const size_t grl = (size_t)(by * BM + rb + mi * 16) * NROWS;
        const size_t grh = grl + (size_t)8 * NROWS;
        float* ylo = y_out + grl;
        float* yhi = y_out + grh;
        #pragma unroll
        for (int ni = 0; ni < 8; ni++) {
            const int c  = cb + ni * 8;
            const int gc = bx * BN + c;
            float v00 = acc[mi][ni][0], v01 = acc[mi][ni][1];
            float v10 = acc[mi][ni][2], v11 = acc[mi][ni][3];

            *(float2*)(out + grl + gc) = make_float2(v00, v01);
            *(float2*)(out + grh + gc) = make_float2(v10, v11);

            const int lc0 = slc[c], lc1 = slc[c + 1];

            float l00 = v00 * INVT, l01 = v01 * INVT;
            float l10 = v10 * INVT, l11 = v11 * INVT;
            pe[sl] += __expf(l00) + __expf(l01);
            pe[sh] += __expf(l10) + __expf(l11);

            const int e00 = (lr_lo == lc0), e01 = (lr_lo == lc1);
            const int e10 = (lr_hi == lc0), e11 = (lr_hi == lc1);

            // y_true (scalar: y_out base = d_out + N*N + 1, 4B-aligned only)
            ylo[gc]     = e00 ? 1.0f : 0.0f;
            ylo[gc + 1] = e01 ? 1.0f : 0.0f;
            yhi[gc]     = e10 ? 1.0f : 0.0f;
            yhi[gc + 1] = e11 ? 1.0f : 0.0f;

            pl[sl] += (e00 ? l00 : 0.f) + (e01 ? l01 : 0.f);
            pl[sh] += (e10 ? l10 : 0.f) + (e11 ? l11 : 0.f);
        }
    }

    #pragma unroll
    for (int s = 0; s < 4; s++) {
        pe[s] += __shfl_xor_sync(0xffffffffu, pe[s], 1);
        pe[s] += __shfl_xor_sync(0xffffffffu, pe[s], 2);
        pl[s] += __shfl_xor_sync(0xffffffffu, pl[s], 1);
        pl[s] += __shfl_xor_sync(0xffffffffu, pl[s], 2);
    }
    if ((lane & 3) == 0) {
        const int pc = bx * 2 + wn;
        #pragma unroll
        for (int s = 0; s < 4; s++) {
            int grow = by * BM + rb + (s >> 1) * 16 + (s & 1) * 8;
            g_pe[(size_t)grow * PARTW + pc] = pe[s];
            g_pl[(size_t)grow * PARTW + pc] = pl[s];
        }
    }
}

// ============================================================
// Kernel 3: row_val[i] = sum_l/cnt - log(sum_e)  (32 rows/block)
// ============================================================
__global__ __launch_bounds__(1024)
void rowval_kernel(const int* __restrict__ labels) {
    __shared__ int hist[64];
    const int t = threadIdx.x;
    if (t < 64) hist[t] = 0;
    __syncthreads();

    int4 lb = ((const int4*)labels)[t];
    atomicAdd(&hist[lb.x], 1);
    atomicAdd(&hist[lb.y], 1);
    atomicAdd(&hist[lb.z], 1);
    atomicAdd(&hist[lb.w], 1);
    __syncthreads();

    const int w    = t >> 5;
    const int lane = t & 31;
    const int row  = blockIdx.x * 32 + w;

    float2 e2 = *(const float2*)&g_pe[(size_t)row * PARTW + lane * 2];
    float2 l2 = *(const float2*)&g_pl[(size_t)row * PARTW + lane * 2];
    float se = e2.x + e2.y;
    float sl = l2.x + l2.y;
    #pragma unroll
    for (int o = 16; o > 0; o >>= 1) {
        se += __shfl_xor_sync(0xffffffffu, se, o);
        sl += __shfl_xor_sync(0xffffffffu, sl, o);
    }
    if (lane == 0) {
        float cnt = (float)hist[labels[row]];
        g_row_val[row] = sl / cnt - __logf(se);
    }
}

// ============================================================
// Kernel 4: loss = -mean(row_val)
// ============================================================
__global__ __launch_bounds__(1024)
void loss_kernel(float* __restrict__ out_loss) {
    const int t = threadIdx.x;
    float4 v = *(const float4*)(g_row_val + t * 4);
    float sum = v.x + v.y + v.z + v.w;
    #pragma unroll
    for (int o = 16; o > 0; o >>= 1)
        sum += __shfl_xor_sync(0xffffffffu, sum, o);
    __shared__ float red[32];
    if ((t & 31) == 0) red[t >> 5] = sum;
    __syncthreads();
    if (t < 32) {
        float x = red[t];
        #pragma unroll
        for (int o = 16; o > 0; o >>= 1)
            x += __shfl_xor_sync(0xffffffffu, x, o);
        if (t == 0) out_loss[0] = -(x / (float)NROWS);
    }
}

// ============================================================
// launch — clean 4-node chain; y_true lives in the GEMM epilogue
// ============================================================
extern "C" void kernel_launch(void* const* d_in, const int* in_sizes, int n_in,
                              void* d_out, int out_size) {
    const float* c      = (const float*)d_in[0];
    const float* ch     = (const float*)d_in[1];
    const int*   labels = (const int*)d_in[2];

    float* out   = (float*)d_out;
    float* sim   = out;
    float* loss  = out + (size_t)NROWS * NROWS;
    float* ytrue = out + (size_t)NROWS * NROWS + 1;

    normalize_kernel<<<2 * NROWS, 256>>>(c, ch);

    cudaFuncSetAttribute(gemm_fused_kernel, cudaFuncAttributeMaxDynamicSharedMemorySize,
                         SMEM_DYN_BYTES);
    dim3 grid(NROWS / BN, NROWS / BM);
    gemm_fused_kernel<<<grid, 256, SMEM_DYN_BYTES>>>(sim, labels, ytrue);

    rowval_kernel<<<NROWS / 32, 1024>>>(labels);

    loss_kernel<<<1, 1024>>>(loss);
}

// round 14
// speedup vs baseline: 1.0860x; 1.0860x over previous
#include <cuda_runtime.h>
#include <cuda_fp16.h>
#include <math.h>
#include <stdint.h>

#define NROWS 4096
#define DIM   1024
#define TEMPF 0.05f
#define INVT  20.0f
#define EPSF  1e-8f

#define KSTORE 1024
#define BM 128
#define BN 128
#define BK 64
#define NCHUNKS (KSTORE / BK)       // 16
#define NSTAGES 3
#define A_STAGE_BYTES (BM * 128)
#define B_STAGE_BYTES (BN * 128)
#define STAGE_BYTES   (A_STAGE_BYTES + B_STAGE_BYTES)
#define SMEM_DYN_BYTES (NSTAGES * STAGE_BYTES)          // 96 KB -> 2 CTAs/SM

#define NTILES (NROWS / BN)          // 32 column tiles
#define PARTW  (NTILES * 2)          // 64 partials per row

// -------- device scratch --------
__device__ __half g_a[(size_t)NROWS * KSTORE];
__device__ __half g_b[(size_t)NROWS * KSTORE];
__device__ __align__(16) float g_pe[(size_t)NROWS * PARTW];
__device__ __align__(16) float g_pl[(size_t)NROWS * PARTW];
__device__ __align__(16) float g_row_val[NROWS];

// ============================================================
// helpers
// ============================================================
__device__ __forceinline__ uint32_t smem_u32(const void* p) {
    uint32_t a;
    asm("{ .reg .u64 t; cvta.to.shared.u64 t, %1; cvt.u32.u64 %0, t; }"
        : "=r"(a) : "l"(p));
    return a;
}

#define SW128(x) ((x) ^ (((x) >> 3) & 0x70))

__device__ __forceinline__ void cp_async16(uint32_t dst, const void* src) {
    asm volatile("cp.async.cg.shared.global [%0], [%1], 16;\n" :: "r"(dst), "l"(src));
}

__device__ __forceinline__ void ldsm_x4(uint32_t addr, uint32_t& r0, uint32_t& r1,
                                        uint32_t& r2, uint32_t& r3) {
    asm volatile("ldmatrix.sync.aligned.m8n8.x4.shared.b16 {%0,%1,%2,%3}, [%4];"
                 : "=r"(r0), "=r"(r1), "=r"(r2), "=r"(r3) : "r"(addr));
}

__device__ __forceinline__ void mma16816(float& c0, float& c1, float& c2, float& c3,
                                         uint32_t a0, uint32_t a1, uint32_t a2, uint32_t a3,
                                         uint32_t b0, uint32_t b1) {
    asm volatile(
        "mma.sync.aligned.m16n8k16.row.col.f32.f16.f16.f32 "
        "{%0,%1,%2,%3}, {%4,%5,%6,%7}, {%8,%9}, {%0,%1,%2,%3};"
        : "+f"(c0), "+f"(c1), "+f"(c2), "+f"(c3)
        : "r"(a0), "r"(a1), "r"(a2), "r"(a3), "r"(b0), "r"(b1));
}

// ============================================================
// Kernel 1: row-normalize -> fp16
// ============================================================
__global__ __launch_bounds__(256)
void normalize_kernel(const float* __restrict__ c, const float* __restrict__ ch) {
    int row = blockIdx.x;
    bool isC = (row < NROWS);
    int r = isC ? row : row - NROWS;
    const float4* srow = (const float4*)((isC ? c : ch) + (size_t)r * DIM);

    int t = threadIdx.x;
    float4 v = srow[t];
    float ssq = v.x * v.x + v.y * v.y + v.z * v.z + v.w * v.w;

    #pragma unroll
    for (int o = 16; o > 0; o >>= 1)
        ssq += __shfl_xor_sync(0xffffffffu, ssq, o);

    __shared__ float wsum[8];
    if ((t & 31) == 0) wsum[t >> 5] = ssq;
    __syncthreads();
    float tot = 0.f;
    #pragma unroll
    for (int w = 0; w < 8; w++) tot += wsum[w];

    float rinv = 1.0f / fmaxf(sqrtf(tot), EPSF);

    union { __half h[4]; uint2 u; } ph;
    ph.h[0] = __float2half_rn(v.x * rinv);
    ph.h[1] = __float2half_rn(v.y * rinv);
    ph.h[2] = __float2half_rn(v.z * rinv);
    ph.h[3] = __float2half_rn(v.w * rinv);

    __half* dst = (isC ? g_a : g_b) + (size_t)r * KSTORE + t * 4;
    *(uint2*)dst = ph.u;
}

// ============================================================
// Kernel 2: fused fp16 GEMM + sim write + softmax partials
// ============================================================
__device__ __forceinline__ void load_chunk(const __half* gA, const __half* gB,
                                           int kc, uint32_t sA, uint32_t sB, int t) {
    int ke = kc * BK;
    #pragma unroll
    for (int i = 0; i < 4; i++) {
        int idx = i * 256 + t;
        int r = idx >> 3, cb = idx & 7;
        cp_async16(sA + SW128(r * 128 + cb * 16), gA + (size_t)r * KSTORE + ke + cb * 8);
    }
    #pragma unroll
    for (int i = 0; i < 4; i++) {
        int idx = i * 256 + t;
        int r = idx >> 3, cb = idx & 7;
        cp_async16(sB + SW128(r * 128 + cb * 16), gB + (size_t)r * KSTORE + ke + cb * 8);
    }
    asm volatile("cp.async.commit_group;\n" ::: "memory");
}

__global__ __launch_bounds__(256, 2)
void gemm_fused_kernel(float* __restrict__ out,
                       const int* __restrict__ labels) {
    extern __shared__ char dyn_smem[];
    __shared__ int slr[BM];
    __shared__ int slc[BN];

    const int t    = threadIdx.x;
    const int wid  = t >> 5;
    const int lane = t & 31;
    const int wm   = wid >> 1;
    const int wn   = wid & 1;
    const int bx   = blockIdx.x;
    const int by   = blockIdx.y;

    uint32_t smem = smem_u32(dyn_smem);

    if (t < BM) slr[t] = labels[by * BM + t];
    else if (t < BM + BN) slc[t - BM] = labels[bx * BN + (t - BM)];

    const __half* gA = g_a + (size_t)by * BM * KSTORE;
    const __half* gB = g_b + (size_t)bx * BN * KSTORE;

    float acc[2][8][4];
    #pragma unroll
    for (int mi = 0; mi < 2; mi++)
        #pragma unroll
        for (int ni = 0; ni < 8; ni++)
            #pragma unroll
            for (int q = 0; q < 4; q++) acc[mi][ni][q] = 0.f;

    load_chunk(gA, gB, 0, smem, smem + A_STAGE_BYTES, t);
    load_chunk(gA, gB, 1, smem + STAGE_BYTES, smem + STAGE_BYTES + A_STAGE_BYTES, t);

    const int a_row_in16 = lane & 15;
    const int a_kadd     = ((lane >> 4) & 1) * 16;
    const int b_row_in16 = (lane & 7) + (((lane >> 4) & 1) << 3);
    const int b_kadd     = ((lane >> 3) & 1) * 16;

    for (int kc = 0; kc < NCHUNKS; kc++) {
        if (kc + 2 < NCHUNKS) {
            int s = (kc + 2) % NSTAGES;
            load_chunk(gA, gB, kc + 2, smem + s * STAGE_BYTES,
                       smem + s * STAGE_BYTES + A_STAGE_BYTES, t);
        } else {
            asm volatile("cp.async.commit_group;\n" ::: "memory");
        }

        asm volatile("cp.async.wait_group 2;\n" ::: "memory");
        __syncthreads();

        uint32_t sA = smem + (kc % NSTAGES) * STAGE_BYTES;
        uint32_t sB = sA + A_STAGE_BYTES;

        #pragma unroll
        for (int ks = 0; ks < 4; ks++) {
            const int kb = ks * 32;

            uint32_t af[2][4];
            #pragma unroll
            for (int mi = 0; mi < 2; mi++) {
                int row = wm * 32 + mi * 16 + a_row_in16;
                ldsm_x4(sA + SW128(row * 128 + kb + a_kadd),
                        af[mi][0], af[mi][1], af[mi][2], af[mi][3]);
            }
            uint32_t bf[4][4];
            #pragma unroll
            for (int nj = 0; nj < 4; nj++) {
                int row = wn * 64 + nj * 16 + b_row_in16;
                ldsm_x4(sB + SW128(row * 128 + kb + b_kadd),
                        bf[nj][0], bf[nj][1], bf[nj][2], bf[nj][3]);
            }
            #pragma unroll
            for (int mi = 0; mi < 2; mi++)
                #pragma unroll
                for (int nj = 0; nj < 4; nj++) {
                    mma16816(acc[mi][nj * 2 + 0][0], acc[mi][nj * 2 + 0][1],
                             acc[mi][nj * 2 + 0][2], acc[mi][nj * 2 + 0][3],
                             af[mi][0], af[mi][1], af[mi][2], af[mi][3],
                             bf[nj][0], bf[nj][1]);
                    mma16816(acc[mi][nj * 2 + 1][0], acc[mi][nj * 2 + 1][1],
                             acc[mi][nj * 2 + 1][2], acc[mi][nj * 2 + 1][3],
                             af[mi][0], af[mi][1], af[mi][2], af[mi][3],
                             bf[nj][2], bf[nj][3]);
                }
        }
        __syncthreads();
    }

    // ---------- fused epilogue: sim stores + softmax partials ----------
    const int rb = wm * 32 + (lane >> 2);
    const int cb = wn * 64 + (lane & 3) * 2;

    float pe[4] = {0.f, 0.f, 0.f, 0.f};
    float pl[4] = {0.f, 0.f, 0.f, 0.f};

    #pragma unroll
    for (int mi = 0; mi < 2; mi++) {
        const int sl = mi * 2, sh = mi * 2 + 1;
        const int lr_lo = slr[rb + mi * 16];
        const int lr_hi = slr[rb + mi * 16 + 8];
        const size_t grl = (size_t)(by * BM + rb + mi * 16) * NROWS;
        const size_t grh = grl + (size_t)8 * NROWS;
        #pragma unroll
        for (int ni = 0; ni < 8; ni++) {
            const int c  = cb + ni * 8;
            const int gc = bx * BN + c;
            float v00 = acc[mi][ni][0], v01 = acc[mi][ni][1];
            float v10 = acc[mi][ni][2], v11 = acc[mi][ni][3];

            *(float2*)(out + grl + gc) = make_float2(v00, v01);
            *(float2*)(out + grh + gc) = make_float2(v10, v11);

            const int lc0 = slc[c], lc1 = slc[c + 1];

            float l00 = v00 * INVT, l01 = v01 * INVT;
            float l10 = v10 * INVT, l11 = v11 * INVT;
            pe[sl] += __expf(l00) + __expf(l01);
            pe[sh] += __expf(l10) + __expf(l11);

            pl[sl] += ((lr_lo == lc0) ? l00 : 0.f) + ((lr_lo == lc1) ? l01 : 0.f);
            pl[sh] += ((lr_hi == lc0) ? l10 : 0.f) + ((lr_hi == lc1) ? l11 : 0.f);
        }
    }

    #pragma unroll
    for (int s = 0; s < 4; s++) {
        pe[s] += __shfl_xor_sync(0xffffffffu, pe[s], 1);
        pe[s] += __shfl_xor_sync(0xffffffffu, pe[s], 2);
        pl[s] += __shfl_xor_sync(0xffffffffu, pl[s], 1);
        pl[s] += __shfl_xor_sync(0xffffffffu, pl[s], 2);
    }
    if ((lane & 3) == 0) {
        const int pc = bx * 2 + wn;
        #pragma unroll
        for (int s = 0; s < 4; s++) {
            int grow = by * BM + rb + (s >> 1) * 16 + (s & 1) * 8;
            g_pe[(size_t)grow * PARTW + pc] = pe[s];
            g_pl[(size_t)grow * PARTW + pc] = pl[s];
        }
    }
}

// ============================================================
// Kernel 3: y_true — forked AFTER normalize so its 67 MB of
// coalesced HBM writes drain underneath the tensor-bound GEMM
// (GEMM: 2 CTAs/SM = 16/64 warp slots, DRAM ~20% -> spare
// capacity on both axes).
// ============================================================
__global__ __launch_bounds__(256)
void ytrue_kernel(const int* __restrict__ labels, float* __restrict__ y_out) {
    const int i = blockIdx.x;
    const int t = threadIdx.x;
    const int li = labels[i];
    float* yrow = y_out + (size_t)i * NROWS;
    #pragma unroll
    for (int k = 0; k < NROWS / 256; k++) {
        int j = k * 256 + t;
        yrow[j] = (labels[j] == li) ? 1.0f : 0.0f;
    }
}

// ============================================================
// Kernel 4: row_val[i] = sum_l/cnt - log(sum_e)  (32 rows/block)
// ============================================================
__global__ __launch_bounds__(1024)
void rowval_kernel(const int* __restrict__ labels) {
    __shared__ int hist[64];
    const int t = threadIdx.x;
    if (t < 64) hist[t] = 0;
    __syncthreads();

    int4 lb = ((const int4*)labels)[t];
    atomicAdd(&hist[lb.x], 1);
    atomicAdd(&hist[lb.y], 1);
    atomicAdd(&hist[lb.z], 1);
    atomicAdd(&hist[lb.w], 1);
    __syncthreads();

    const int w    = t >> 5;
    const int lane = t & 31;
    const int row  = blockIdx.x * 32 + w;

    float2 e2 = *(const float2*)&g_pe[(size_t)row * PARTW + lane * 2];
    float2 l2 = *(const float2*)&g_pl[(size_t)row * PARTW + lane * 2];
    float se = e2.x + e2.y;
    float sl = l2.x + l2.y;
    #pragma unroll
    for (int o = 16; o > 0; o >>= 1) {
        se += __shfl_xor_sync(0xffffffffu, se, o);
        sl += __shfl_xor_sync(0xffffffffu, sl, o);
    }
    if (lane == 0) {
        float cnt = (float)hist[labels[row]];
        g_row_val[row] = sl / cnt - __logf(se);
    }
}

// ============================================================
// Kernel 5: loss = -mean(row_val)
// ============================================================
__global__ __launch_bounds__(1024)
void loss_kernel(float* __restrict__ out_loss) {
    const int t = threadIdx.x;
    float4 v = *(const float4*)(g_row_val + t * 4);
    float sum = v.x + v.y + v.z + v.w;
    #pragma unroll
    for (int o = 16; o > 0; o >>= 1)
        sum += __shfl_xor_sync(0xffffffffu, sum, o);
    __shared__ float red[32];
    if ((t & 31) == 0) red[t >> 5] = sum;
    __syncthreads();
    if (t < 32) {
        float x = red[t];
        #pragma unroll
        for (int o = 16; o > 0; o >>= 1)
            x += __shfl_xor_sync(0xffffffffu, x, o);
        if (t == 0) out_loss[0] = -(x / (float)NROWS);
    }
}

// ============================================================
// launch — fork ytrue AFTER normalize, concurrent with the GEMM
// ============================================================
extern "C" void kernel_launch(void* const* d_in, const int* in_sizes, int n_in,
                              void* d_out, int out_size) {
    const float* c      = (const float*)d_in[0];
    const float* ch     = (const float*)d_in[1];
    const int*   labels = (const int*)d_in[2];

    float* out   = (float*)d_out;
    float* sim   = out;
    float* loss  = out + (size_t)NROWS * NROWS;
    float* ytrue = out + (size_t)NROWS * NROWS + 1;

    cudaStream_t s2;
    cudaEvent_t evFork, evJoin;
    cudaStreamCreateWithFlags(&s2, cudaStreamNonBlocking);
    cudaEventCreateWithFlags(&evFork, cudaEventDisableTiming);
    cudaEventCreateWithFlags(&evJoin, cudaEventDisableTiming);

    normalize_kernel<<<2 * NROWS, 256>>>(c, ch);

    // fork AFTER normalize: ytrue overlaps the tensor-bound GEMM
    cudaEventRecord(evFork, 0);
    cudaStreamWaitEvent(s2, evFork, 0);
    ytrue_kernel<<<NROWS, 256, 0, s2>>>(labels, ytrue);
    cudaEventRecord(evJoin, s2);

    cudaFuncSetAttribute(gemm_fused_kernel, cudaFuncAttributeMaxDynamicSharedMemorySize,
                         SMEM_DYN_BYTES);
    dim3 grid(NROWS / BN, NROWS / BM);
    gemm_fused_kernel<<<grid, 256, SMEM_DYN_BYTES>>>(sim, labels);

    rowval_kernel<<<NROWS / 32, 1024>>>(labels);
    loss_kernel<<<1, 1024>>>(loss);

    // join so the captured graph has a single sink
    cudaStreamWaitEvent(0, evJoin, 0);

    cudaEventDestroy(evFork);
    cudaEventDestroy(evJoin);
    cudaStreamDestroy(s2);
}

// round 15
// speedup vs baseline: 1.1382x; 1.0480x over previous
#include <cuda_runtime.h>
#include <cuda_fp16.h>
#include <math.h>
#include <stdint.h>

#define NROWS 4096
#define DIM   1024
#define TEMPF 0.05f
#define INVT  20.0f
#define EPSF  1e-8f

#define KSTORE 1024
#define BM 128
#define BN 128
#define BK 64
#define NCHUNKS (KSTORE / BK)       // 16
#define NSTAGES 3
#define A_STAGE_BYTES (BM * 128)
#define B_STAGE_BYTES (BN * 128)
#define STAGE_BYTES   (A_STAGE_BYTES + B_STAGE_BYTES)
#define SMEM_DYN_BYTES (NSTAGES * STAGE_BYTES)          // 96 KB -> 2 CTAs/SM

#define NTILES (NROWS / BN)          // 32 column tiles
#define PARTW  (NTILES * 2)          // 64 partials per row

#define RV_BLOCKS (NROWS / 32)       // 128 rowval blocks

// -------- device scratch --------
__device__ __half g_a[(size_t)NROWS * KSTORE];
__device__ __half g_b[(size_t)NROWS * KSTORE];
__device__ __align__(16) float g_pe[(size_t)NROWS * PARTW];
__device__ __align__(16) float g_pl[(size_t)NROWS * PARTW];
__device__ __align__(16) float g_row_val[NROWS];
__device__ int g_rv_done = 0;        // last-block counter (self-resetting)

// ============================================================
// helpers
// ============================================================
__device__ __forceinline__ uint32_t smem_u32(const void* p) {
    uint32_t a;
    asm("{ .reg .u64 t; cvta.to.shared.u64 t, %1; cvt.u32.u64 %0, t; }"
        : "=r"(a) : "l"(p));
    return a;
}

#define SW128(x) ((x) ^ (((x) >> 3) & 0x70))

__device__ __forceinline__ void cp_async16(uint32_t dst, const void* src) {
    asm volatile("cp.async.cg.shared.global [%0], [%1], 16;\n" :: "r"(dst), "l"(src));
}

__device__ __forceinline__ void ldsm_x4(uint32_t addr, uint32_t& r0, uint32_t& r1,
                                        uint32_t& r2, uint32_t& r3) {
    asm volatile("ldmatrix.sync.aligned.m8n8.x4.shared.b16 {%0,%1,%2,%3}, [%4];"
                 : "=r"(r0), "=r"(r1), "=r"(r2), "=r"(r3) : "r"(addr));
}

__device__ __forceinline__ void mma16816(float& c0, float& c1, float& c2, float& c3,
                                         uint32_t a0, uint32_t a1, uint32_t a2, uint32_t a3,
                                         uint32_t b0, uint32_t b1) {
    asm volatile(
        "mma.sync.aligned.m16n8k16.row.col.f32.f16.f16.f32 "
        "{%0,%1,%2,%3}, {%4,%5,%6,%7}, {%8,%9}, {%0,%1,%2,%3};"
        : "+f"(c0), "+f"(c1), "+f"(c2), "+f"(c3)
        : "r"(a0), "r"(a1), "r"(a2), "r"(a3), "r"(b0), "r"(b1));
}

// ============================================================
// Kernel 1: row-normalize -> fp16, one WARP per row (no block sync)
// grid = 2*NROWS/8 blocks of 256 threads (8 warps)
// ============================================================
__global__ __launch_bounds__(256)
void normalize_kernel(const float* __restrict__ c, const float* __restrict__ ch) {
    const int warp = (blockIdx.x * 8) + (threadIdx.x >> 5);
    const int lane = threadIdx.x & 31;
    const bool isC = (warp < NROWS);
    const int r = isC ? warp : warp - NROWS;

    const float4* srow = (const float4*)((isC ? c : ch) + (size_t)r * DIM);

    float4 v[8];
    float ssq = 0.f;
    #pragma unroll
    for (int i = 0; i < 8; i++) {
        v[i] = srow[lane + i * 32];
        ssq += v[i].x * v[i].x + v[i].y * v[i].y + v[i].z * v[i].z + v[i].w * v[i].w;
    }
    #pragma unroll
    for (int o = 16; o > 0; o >>= 1)
        ssq += __shfl_xor_sync(0xffffffffu, ssq, o);

    float rinv = 1.0f / fmaxf(sqrtf(ssq), EPSF);

    __half* dst = (isC ? g_a : g_b) + (size_t)r * KSTORE;
    #pragma unroll
    for (int i = 0; i < 8; i++) {
        union { __half h[4]; uint2 u; } ph;
        ph.h[0] = __float2half_rn(v[i].x * rinv);
        ph.h[1] = __float2half_rn(v[i].y * rinv);
        ph.h[2] = __float2half_rn(v[i].z * rinv);
        ph.h[3] = __float2half_rn(v[i].w * rinv);
        *(uint2*)(dst + (lane + i * 32) * 4) = ph.u;
    }
}

// ============================================================
// Kernel 2: fused fp16 GEMM + sim write + softmax partials
// ============================================================
__device__ __forceinline__ void load_chunk(const __half* gA, const __half* gB,
                                           int kc, uint32_t sA, uint32_t sB, int t) {
    int ke = kc * BK;
    #pragma unroll
    for (int i = 0; i < 4; i++) {
        int idx = i * 256 + t;
        int r = idx >> 3, cb = idx & 7;
        cp_async16(sA + SW128(r * 128 + cb * 16), gA + (size_t)r * KSTORE + ke + cb * 8);
    }
    #pragma unroll
    for (int i = 0; i < 4; i++) {
        int idx = i * 256 + t;
        int r = idx >> 3, cb = idx & 7;
        cp_async16(sB + SW128(r * 128 + cb * 16), gB + (size_t)r * KSTORE + ke + cb * 8);
    }
    asm volatile("cp.async.commit_group;\n" ::: "memory");
}

__global__ __launch_bounds__(256, 2)
void gemm_fused_kernel(float* __restrict__ out,
                       const int* __restrict__ labels) {
    extern __shared__ char dyn_smem[];
    __shared__ int slr[BM];
    __shared__ int slc[BN];

    const int t    = threadIdx.x;
    const int wid  = t >> 5;
    const int lane = t & 31;
    const int wm   = wid >> 1;
    const int wn   = wid & 1;
    const int bx   = blockIdx.x;
    const int by   = blockIdx.y;

    uint32_t smem = smem_u32(dyn_smem);

    if (t < BM) slr[t] = labels[by * BM + t];
    else if (t < BM + BN) slc[t - BM] = labels[bx * BN + (t - BM)];

    const __half* gA = g_a + (size_t)by * BM * KSTORE;
    const __half* gB = g_b + (size_t)bx * BN * KSTORE;

    float acc[2][8][4];
    #pragma unroll
    for (int mi = 0; mi < 2; mi++)
        #pragma unroll
        for (int ni = 0; ni < 8; ni++)
            #pragma unroll
            for (int q = 0; q < 4; q++) acc[mi][ni][q] = 0.f;

    load_chunk(gA, gB, 0, smem, smem + A_STAGE_BYTES, t);
    load_chunk(gA, gB, 1, smem + STAGE_BYTES, smem + STAGE_BYTES + A_STAGE_BYTES, t);

    const int a_row_in16 = lane & 15;
    const int a_kadd     = ((lane >> 4) & 1) * 16;
    const int b_row_in16 = (lane & 7) + (((lane >> 4) & 1) << 3);
    const int b_kadd     = ((lane >> 3) & 1) * 16;

    for (int kc = 0; kc < NCHUNKS; kc++) {
        if (kc + 2 < NCHUNKS) {
            int s = (kc + 2) % NSTAGES;
            load_chunk(gA, gB, kc + 2, smem + s * STAGE_BYTES,
                       smem + s * STAGE_BYTES + A_STAGE_BYTES, t);
        } else {
            asm volatile("cp.async.commit_group;\n" ::: "memory");
        }

        asm volatile("cp.async.wait_group 2;\n" ::: "memory");
        __syncthreads();

        uint32_t sA = smem + (kc % NSTAGES) * STAGE_BYTES;
        uint32_t sB = sA + A_STAGE_BYTES;

        #pragma unroll
        for (int ks = 0; ks < 4; ks++) {
            const int kb = ks * 32;

            uint32_t af[2][4];
            #pragma unroll
            for (int mi = 0; mi < 2; mi++) {
                int row = wm * 32 + mi * 16 + a_row_in16;
                ldsm_x4(sA + SW128(row * 128 + kb + a_kadd),
                        af[mi][0], af[mi][1], af[mi][2], af[mi][3]);
            }
            uint32_t bf[4][4];
            #pragma unroll
            for (int nj = 0; nj < 4; nj++) {
                int row = wn * 64 + nj * 16 + b_row_in16;
                ldsm_x4(sB + SW128(row * 128 + kb + b_kadd),
                        bf[nj][0], bf[nj][1], bf[nj][2], bf[nj][3]);
            }
            #pragma unroll
            for (int mi = 0; mi < 2; mi++)
                #pragma unroll
                for (int nj = 0; nj < 4; nj++) {
                    mma16816(acc[mi][nj * 2 + 0][0], acc[mi][nj * 2 + 0][1],
                             acc[mi][nj * 2 + 0][2], acc[mi][nj * 2 + 0][3],
                             af[mi][0], af[mi][1], af[mi][2], af[mi][3],
                             bf[nj][0], bf[nj][1]);
                    mma16816(acc[mi][nj * 2 + 1][0], acc[mi][nj * 2 + 1][1],
                             acc[mi][nj * 2 + 1][2], acc[mi][nj * 2 + 1][3],
                             af[mi][0], af[mi][1], af[mi][2], af[mi][3],
                             bf[nj][2], bf[nj][3]);
                }
        }
        __syncthreads();
    }

    // ---------- fused epilogue: sim stores + softmax partials ----------
    const int rb = wm * 32 + (lane >> 2);
    const int cb = wn * 64 + (lane & 3) * 2;

    float pe[4] = {0.f, 0.f, 0.f, 0.f};
    float pl[4] = {0.f, 0.f, 0.f, 0.f};

    #pragma unroll
    for (int mi = 0; mi < 2; mi++) {
        const int sl = mi * 2, sh = mi * 2 + 1;
        const int lr_lo = slr[rb + mi * 16];
        const int lr_hi = slr[rb + mi * 16 + 8];
        const size_t grl = (size_t)(by * BM + rb + mi * 16) * NROWS;
        const size_t grh = grl + (size_t)8 * NROWS;
        #pragma unroll
        for (int ni = 0; ni < 8; ni++) {
            const int c  = cb + ni * 8;
            const int gc = bx * BN + c;
            float v00 = acc[mi][ni][0], v01 = acc[mi][ni][1];
            float v10 = acc[mi][ni][2], v11 = acc[mi][ni][3];

            *(float2*)(out + grl + gc) = make_float2(v00, v01);
            *(float2*)(out + grh + gc) = make_float2(v10, v11);

            const int lc0 = slc[c], lc1 = slc[c + 1];

            float l00 = v00 * INVT, l01 = v01 * INVT;
            float l10 = v10 * INVT, l11 = v11 * INVT;
            pe[sl] += __expf(l00) + __expf(l01);
            pe[sh] += __expf(l10) + __expf(l11);

            pl[sl] += ((lr_lo == lc0) ? l00 : 0.f) + ((lr_lo == lc1) ? l01 : 0.f);
            pl[sh] += ((lr_hi == lc0) ? l10 : 0.f) + ((lr_hi == lc1) ? l11 : 0.f);
        }
    }

    #pragma unroll
    for (int s = 0; s < 4; s++) {
        pe[s] += __shfl_xor_sync(0xffffffffu, pe[s], 1);
        pe[s] += __shfl_xor_sync(0xffffffffu, pe[s], 2);
        pl[s] += __shfl_xor_sync(0xffffffffu, pl[s], 1);
        pl[s] += __shfl_xor_sync(0xffffffffu, pl[s], 2);
    }
    if ((lane & 3) == 0) {
        const int pc = bx * 2 + wn;
        #pragma unroll
        for (int s = 0; s < 4; s++) {
            int grow = by * BM + rb + (s >> 1) * 16 + (s & 1) * 8;
            g_pe[(size_t)grow * PARTW + pc] = pe[s];
            g_pl[(size_t)grow * PARTW + pc] = pl[s];
        }
    }
}

// ============================================================
// Kernel 3: y_true — forked AFTER the GEMM (overlaps rowval tail)
// ============================================================
__global__ __launch_bounds__(256)
void ytrue_kernel(const int* __restrict__ labels, float* __restrict__ y_out) {
    const int i = blockIdx.x;
    const int t = threadIdx.x;
    const int li = labels[i];
    float* yrow = y_out + (size_t)i * NROWS;
    #pragma unroll
    for (int k = 0; k < NROWS / 256; k++) {
        int j = k * 256 + t;
        yrow[j] = (labels[j] == li) ? 1.0f : 0.0f;
    }
}

// ============================================================
// Kernel 4: rowval + fused loss (last-block reduction)
// ============================================================
__global__ __launch_bounds__(1024)
void rowval_loss_kernel(const int* __restrict__ labels,
                        float* __restrict__ out_loss) {
    __shared__ int hist[64];
    __shared__ bool is_last;
    const int t = threadIdx.x;
    if (t < 64) hist[t] = 0;
    __syncthreads();

    int4 lb = ((const int4*)labels)[t];
    atomicAdd(&hist[lb.x], 1);
    atomicAdd(&hist[lb.y], 1);
    atomicAdd(&hist[lb.z], 1);
    atomicAdd(&hist[lb.w], 1);
    __syncthreads();

    const int w    = t >> 5;
    const int lane = t & 31;
    const int row  = blockIdx.x * 32 + w;

    float2 e2 = *(const float2*)&g_pe[(size_t)row * PARTW + lane * 2];
    float2 l2 = *(const float2*)&g_pl[(size_t)row * PARTW + lane * 2];
    float se = e2.x + e2.y;
    float sl = l2.x + l2.y;
    #pragma unroll
    for (int o = 16; o > 0; o >>= 1) {
        se += __shfl_xor_sync(0xffffffffu, se, o);
        sl += __shfl_xor_sync(0xffffffffu, sl, o);
    }
    if (lane == 0) {
        float cnt = (float)hist[labels[row]];
        g_row_val[row] = sl / cnt - __logf(se);
    }

    // last-block loss reduction (deterministic: fixed block, fixed order)
    __threadfence();
    __syncthreads();
    if (t == 0) {
        int old = atomicAdd(&g_rv_done, 1);
        is_last = (old == RV_BLOCKS - 1);
    }
    __syncthreads();
    if (is_last) {
        float4 v = *(const float4*)(g_row_val + t * 4);
        float sum = v.x + v.y + v.z + v.w;
        #pragma unroll
        for (int o = 16; o > 0; o >>= 1)
            sum += __shfl_xor_sync(0xffffffffu, sum, o);
        __shared__ float red[32];
        if ((t & 31) == 0) red[t >> 5] = sum;
        __syncthreads();
        if (t < 32) {
            float x = red[t];
            #pragma unroll
            for (int o = 16; o > 0; o >>= 1)
                x += __shfl_xor_sync(0xffffffffu, x, o);
            if (t == 0) {
                out_loss[0] = -(x / (float)NROWS);
                g_rv_done = 0;   // reset for next graph replay
            }
        }
    }
}

// ============================================================
// launch — R12 structure + faster normalize + fused loss
// ============================================================
extern "C" void kernel_launch(void* const* d_in, const int* in_sizes, int n_in,
                              void* d_out, int out_size) {
    const float* c      = (const float*)d_in[0];
    const float* ch     = (const float*)d_in[1];
    const int*   labels = (const int*)d_in[2];

    float* out   = (float*)d_out;
    float* sim   = out;
    float* loss  = out + (size_t)NROWS * NROWS;
    float* ytrue = out + (size_t)NROWS * NROWS + 1;

    cudaStream_t s2;
    cudaEvent_t evFork, evJoin;
    cudaStreamCreateWithFlags(&s2, cudaStreamNonBlocking);
    cudaEventCreateWithFlags(&evFork, cudaEventDisableTiming);
    cudaEventCreateWithFlags(&evJoin, cudaEventDisableTiming);

    normalize_kernel<<<2 * NROWS / 8, 256>>>(c, ch);

    cudaFuncSetAttribute(gemm_fused_kernel, cudaFuncAttributeMaxDynamicSharedMemorySize,
                         SMEM_DYN_BYTES);
    dim3 grid(NROWS / BN, NROWS / BM);
    gemm_fused_kernel<<<grid, 256, SMEM_DYN_BYTES>>>(sim, labels);

    // fork AFTER gemm: ytrue overlaps rowval+loss
    cudaEventRecord(evFork, 0);
    cudaStreamWaitEvent(s2, evFork, 0);
    ytrue_kernel<<<NROWS, 256, 0, s2>>>(labels, ytrue);
    cudaEventRecord(evJoin, s2);

    rowval_loss_kernel<<<RV_BLOCKS, 1024>>>(labels, loss);

    cudaStreamWaitEvent(0, evJoin, 0);

    cudaEventDestroy(evFork);
    cudaEventDestroy(evJoin);
    cudaStreamDestroy(s2);
}